// round 1
// baseline (speedup 1.0000x reference)
#include <cuda_runtime.h>
#include <math.h>

#define BB   8
#define DD   1024
#define NPTS 4096
#define KK   64
#define HH   512

#define SEPS 1e-3f
#define INV_EPS (1.0f/1e-3f)

// ---------------- scratch (device globals; no allocation) ----------------
static __device__ float g_y1[BB*HH*NPTS];      // 64MB
static __device__ float g_y2[BB*HH*NPTS];      // 64MB
static __device__ float g_ls[BB*KK*NPTS];      // 8MB  log_score
static __device__ float g_score[BB*KK*NPTS];   // 8MB
static __device__ float g_lsn[BB*NPTS];        // per (b,n): max + log(sumexp)
static __device__ float g_pi[BB*KK];
static __device__ float g_sc1[HH], g_sh1[HH], g_sc2[HH], g_sh2[HH];
static __device__ float g_muxyz[BB*3*KK];
static __device__ float g_mufea[BB*DD*KK];     // [b][d][k]
static __device__ float g_invf[BB*NPTS];
static __device__ float g_invmu[BB*KK];
static __device__ float g_costx[BB*NPTS*KK];   // [b][n][m]
static __device__ float g_costxT[BB*KK*NPTS];  // [b][m][n]
static __device__ float g_costf[BB*NPTS*KK];
static __device__ float g_costfT[BB*KK*NPTS];
static __device__ float g_u[2*BB*NPTS];
static __device__ float g_v[2*BB*KK];
static __device__ float g_acc[4]; // 0:loss_x sum, 1:loss_f sum, 2:regx sum, 3:regf sum

// ---------------- init ----------------
__global__ void init_kernel() {
    int i = blockIdx.x * blockDim.x + threadIdx.x;
    if (i < 2*BB*NPTS) g_u[i] = 0.0f;
    if (i < 2*BB*KK)   g_v[i] = 0.0f;
    if (i < 4)         g_acc[i] = 0.0f;
}

// ---------------- SGEMM: C[b][m][n] = sum_k W[m][k] * X[b][k][n] + bias[m] --------
template<int BM, int BN, int BK, int TM, int TN>
__global__ __launch_bounds__(256) void sgemm_bias_kernel(
    const float* __restrict__ W, const float* __restrict__ X,
    const float* __restrict__ bias, float* __restrict__ C,
    int M, int Kd)
{
    constexpr int NTX = BN / TN;
    constexpr int NT  = (BM/TM) * (BN/TN);
    const int b  = blockIdx.z;
    const int n0 = blockIdx.x * BN;
    const int m0 = blockIdx.y * BM;
    const float* Xb = X + (size_t)b * Kd * NPTS;
    float* Cb = C + (size_t)b * M * NPTS;

    __shared__ float As[BK][BM];
    __shared__ float Bs[BK][BN];

    const int tid = threadIdx.x;
    const int tx = tid % NTX, ty = tid / NTX;

    float acc[TM][TN];
#pragma unroll
    for (int i = 0; i < TM; i++)
#pragma unroll
        for (int j = 0; j < TN; j++) acc[i][j] = 0.0f;

    for (int k0 = 0; k0 < Kd; k0 += BK) {
#pragma unroll 4
        for (int i = tid; i < BM*BK; i += NT) {
            int m = i / BK, kk = i % BK;
            As[kk][m] = W[(size_t)(m0 + m) * Kd + k0 + kk];
        }
#pragma unroll 4
        for (int i = tid; i < BK*BN; i += NT) {
            int kk = i / BN, n = i % BN;
            Bs[kk][n] = Xb[(size_t)(k0 + kk) * NPTS + n0 + n];
        }
        __syncthreads();
#pragma unroll
        for (int kk = 0; kk < BK; kk++) {
            float a[TM], bb[TN];
#pragma unroll
            for (int i = 0; i < TM; i++) a[i] = As[kk][ty*TM + i];
#pragma unroll
            for (int j = 0; j < TN; j++) bb[j] = Bs[kk][tx*TN + j];
#pragma unroll
            for (int i = 0; i < TM; i++)
#pragma unroll
                for (int j = 0; j < TN; j++) acc[i][j] += a[i] * bb[j];
        }
        __syncthreads();
    }
#pragma unroll
    for (int i = 0; i < TM; i++) {
        float bi = bias[m0 + ty*TM + i];
#pragma unroll
        for (int j = 0; j < TN; j++)
            Cb[(size_t)(m0 + ty*TM + i) * NPTS + n0 + tx*TN + j] = acc[i][j] + bi;
    }
}

// ---------------- BatchNorm stats (per channel over b,n) ----------------
__global__ void bn_stats_kernel(const float* __restrict__ y,
                                const float* __restrict__ g, const float* __restrict__ be,
                                float* __restrict__ sc, float* __restrict__ sh)
{
    int h = blockIdx.x;
    int tid = threadIdx.x;
    float s = 0.0f, s2 = 0.0f;
    for (int b = 0; b < BB; b++) {
        const float* p = y + ((size_t)(b*HH + h)) * NPTS;
        for (int n = tid; n < NPTS; n += 256) { float v = p[n]; s += v; s2 += v*v; }
    }
    __shared__ float r1[256], r2[256];
    r1[tid] = s; r2[tid] = s2; __syncthreads();
    for (int o = 128; o > 0; o >>= 1) {
        if (tid < o) { r1[tid] += r1[tid+o]; r2[tid] += r2[tid+o]; }
        __syncthreads();
    }
    if (tid == 0) {
        float inv = 1.0f / (float)(BB*NPTS);
        float mean = r1[0] * inv;
        float var  = r2[0] * inv - mean*mean;
        float scale = g[h] / sqrtf(var + 1e-5f);
        sc[h] = scale;
        sh[h] = be[h] - mean * scale;
    }
}

__global__ void bn_relu_kernel(float* __restrict__ y,
                               const float* __restrict__ sc, const float* __restrict__ sh)
{
    size_t i4 = (size_t)blockIdx.x * blockDim.x + threadIdx.x;
    size_t total4 = (size_t)BB*HH*NPTS/4;
    if (i4 >= total4) return;
    int h = (int)((i4 / (NPTS/4)) % HH);
    float s = sc[h], t = sh[h];
    float4 v = ((float4*)y)[i4];
    v.x = fmaxf(0.0f, v.x*s + t);
    v.y = fmaxf(0.0f, v.y*s + t);
    v.z = fmaxf(0.0f, v.z*s + t);
    v.w = fmaxf(0.0f, v.w*s + t);
    ((float4*)y)[i4] = v;
}

// ---------------- softmax over K per (b,n) ----------------
__global__ void softmax_kernel() {
    int b = blockIdx.y;
    int n = blockIdx.x * 256 + threadIdx.x;
    const float* base = g_ls + (size_t)b*KK*NPTS + n;
    float mx = -1e30f;
#pragma unroll
    for (int k = 0; k < KK; k++) mx = fmaxf(mx, base[(size_t)k*NPTS]);
    float s = 0.0f;
#pragma unroll
    for (int k = 0; k < KK; k++) s += __expf(base[(size_t)k*NPTS] - mx);
    float inv = 1.0f / s;
    float* sb = g_score + (size_t)b*KK*NPTS + n;
#pragma unroll
    for (int k = 0; k < KK; k++) sb[(size_t)k*NPTS] = __expf(base[(size_t)k*NPTS] - mx) * inv;
    g_lsn[b*NPTS + n] = mx + logf(s);
}

// ---------------- pi = max(sum_n score, 1e-4) ----------------
__global__ void pi_kernel() {
    int k = blockIdx.x, b = blockIdx.y, tid = threadIdx.x;
    const float* p = g_score + (size_t)(b*KK + k) * NPTS;
    float s = 0.0f;
    for (int n = tid; n < NPTS; n += 256) s += p[n];
    __shared__ float r[256];
    r[tid] = s; __syncthreads();
    for (int o = 128; o > 0; o >>= 1) { if (tid < o) r[tid] += r[tid+o]; __syncthreads(); }
    if (tid == 0) g_pi[b*KK + k] = fmaxf(r[0], 1e-4f);
}

// ---------------- mu_xyz ----------------
__global__ void mu_xyz_kernel(const float* __restrict__ xyz) {
    int k = blockIdx.x, b = blockIdx.y, tid = threadIdx.x;
    const float* sp = g_score + (size_t)(b*KK + k) * NPTS;
    const float* x0 = xyz + (size_t)(b*3 + 0) * NPTS;
    const float* x1 = xyz + (size_t)(b*3 + 1) * NPTS;
    const float* x2 = xyz + (size_t)(b*3 + 2) * NPTS;
    float a0 = 0, a1 = 0, a2 = 0;
    for (int n = tid; n < NPTS; n += 256) {
        float s = sp[n];
        a0 += s * x0[n]; a1 += s * x1[n]; a2 += s * x2[n];
    }
    __shared__ float r[256];
    float invpi = 1.0f;
    float acc[3] = {a0, a1, a2};
    for (int d = 0; d < 3; d++) {
        r[tid] = acc[d]; __syncthreads();
        for (int o = 128; o > 0; o >>= 1) { if (tid < o) r[tid] += r[tid+o]; __syncthreads(); }
        if (tid == 0) {
            invpi = 1.0f / g_pi[b*KK + k];
            g_muxyz[(b*3 + d)*KK + k] = r[0] * invpi;
        }
        __syncthreads();
    }
    (void)invpi;
}

// ---------------- mu_fea: [b][d][k] = sum_n F[d,n]*S[k,n] / pi ----------------
__global__ __launch_bounds__(256) void mufea_kernel(const float* __restrict__ feat) {
    int b = blockIdx.y;
    int d0 = blockIdx.x * 64;
    __shared__ float Fs[32][65];
    __shared__ float Ss[32][65];
    int tid = threadIdx.x;
    int tx = tid % 16, ty = tid / 16;
    float acc[4][4];
#pragma unroll
    for (int i = 0; i < 4; i++)
#pragma unroll
        for (int j = 0; j < 4; j++) acc[i][j] = 0.0f;

    for (int n0 = 0; n0 < NPTS; n0 += 32) {
#pragma unroll 8
        for (int i = tid; i < 64*32; i += 256) {
            int dd = i / 32, nn = i % 32;
            Fs[nn][dd] = feat[((size_t)b*DD + d0 + dd) * NPTS + n0 + nn];
        }
#pragma unroll 8
        for (int i = tid; i < 64*32; i += 256) {
            int kk = i / 32, nn = i % 32;
            Ss[nn][kk] = g_score[((size_t)b*KK + kk) * NPTS + n0 + nn];
        }
        __syncthreads();
#pragma unroll
        for (int nn = 0; nn < 32; nn++) {
            float a[4], s[4];
#pragma unroll
            for (int i = 0; i < 4; i++) a[i] = Fs[nn][ty*4 + i];
#pragma unroll
            for (int j = 0; j < 4; j++) s[j] = Ss[nn][tx*4 + j];
#pragma unroll
            for (int i = 0; i < 4; i++)
#pragma unroll
                for (int j = 0; j < 4; j++) acc[i][j] += a[i] * s[j];
        }
        __syncthreads();
    }
#pragma unroll
    for (int i = 0; i < 4; i++)
#pragma unroll
        for (int j = 0; j < 4; j++) {
            int k = tx*4 + j;
            g_mufea[((size_t)b*DD + d0 + ty*4 + i) * KK + k] = acc[i][j] / g_pi[b*KK + k];
        }
}

// ---------------- norms ----------------
__global__ void invf_kernel(const float* __restrict__ feat) {
    int b = blockIdx.y;
    int n = blockIdx.x * 256 + threadIdx.x;
    float s = 0.0f;
    const float* p = feat + (size_t)b*DD*NPTS + n;
    for (int d = 0; d < DD; d++) { float v = p[(size_t)d*NPTS]; s += v*v; }
    g_invf[b*NPTS + n] = 1.0f / fmaxf(sqrtf(s), 1e-12f);
}

__global__ void invmu_kernel() {
    int b = blockIdx.x, k = threadIdx.x;
    float s = 0.0f;
    const float* p = g_mufea + (size_t)b*DD*KK + k;
    for (int d = 0; d < DD; d++) { float v = p[(size_t)d*KK]; s += v*v; }
    g_invmu[b*KK + k] = 1.0f / fmaxf(sqrtf(s), 1e-12f);
}

// ---------------- cost_fea: [b][n][m] = 2 - 2*nf.nmu ----------------
__global__ __launch_bounds__(256) void costf_kernel(const float* __restrict__ feat) {
    int b = blockIdx.y;
    int n0 = blockIdx.x * 128;
    __shared__ float As[16][128];
    __shared__ float Bs[16][64];
    int tid = threadIdx.x;
    int tn = tid % 16, tm = tid / 16;
    float acc[8][4];
#pragma unroll
    for (int i = 0; i < 8; i++)
#pragma unroll
        for (int j = 0; j < 4; j++) acc[i][j] = 0.0f;

    for (int d0 = 0; d0 < DD; d0 += 16) {
#pragma unroll 8
        for (int i = tid; i < 16*128; i += 256) {
            int dd = i / 128, nn = i % 128;
            As[dd][nn] = feat[((size_t)b*DD + d0 + dd) * NPTS + n0 + nn];
        }
#pragma unroll 4
        for (int i = tid; i < 16*64; i += 256) {
            int dd = i / 64, mm = i % 64;
            Bs[dd][mm] = g_mufea[((size_t)b*DD + d0 + dd) * KK + mm];
        }
        __syncthreads();
#pragma unroll
        for (int dd = 0; dd < 16; dd++) {
            float a[8], s[4];
#pragma unroll
            for (int i = 0; i < 8; i++) a[i] = As[dd][tn*8 + i];
#pragma unroll
            for (int j = 0; j < 4; j++) s[j] = Bs[dd][tm*4 + j];
#pragma unroll
            for (int i = 0; i < 8; i++)
#pragma unroll
                for (int j = 0; j < 4; j++) acc[i][j] += a[i] * s[j];
        }
        __syncthreads();
    }
#pragma unroll
    for (int i = 0; i < 8; i++) {
        int n = n0 + tn*8 + i;
        float fi = g_invf[b*NPTS + n];
#pragma unroll
        for (int j = 0; j < 4; j++) {
            int m = tm*4 + j;
            g_costf[((size_t)b*NPTS + n) * KK + m] =
                2.0f - 2.0f * acc[i][j] * fi * g_invmu[b*KK + m];
        }
    }
}

// ---------------- cost_xyz ----------------
__global__ void costx_kernel(const float* __restrict__ xyz) {
    int b = blockIdx.y;
    __shared__ float smu[3][64];
    __shared__ float smun[64];
    int tid = threadIdx.x;
    if (tid < 192) smu[tid/64][tid%64] = g_muxyz[b*3*KK + tid];
    __syncthreads();
    if (tid < 64) smun[tid] = smu[0][tid]*smu[0][tid] + smu[1][tid]*smu[1][tid] + smu[2][tid]*smu[2][tid];
    __syncthreads();
    int w = tid >> 5, l = tid & 31;
    int n = blockIdx.x * 8 + w;
    float x0 = xyz[(size_t)(b*3 + 0)*NPTS + n];
    float x1 = xyz[(size_t)(b*3 + 1)*NPTS + n];
    float x2 = xyz[(size_t)(b*3 + 2)*NPTS + n];
    float xn = x0*x0 + x1*x1 + x2*x2;
    float* row = g_costx + ((size_t)b*NPTS + n) * KK;
#pragma unroll
    for (int t = 0; t < 2; t++) {
        int m = l + t*32;
        float d = x0*smu[0][m] + x1*smu[1][m] + x2*smu[2][m];
        row[m] = xn + smun[m] - 2.0f * d;
    }
}

// ---------------- transpose [b][n][m] -> [b][m][n] ----------------
__global__ void transpose_kernel(const float* __restrict__ src, float* __restrict__ dst) {
    __shared__ float t[32][33];
    int b = blockIdx.z;
    int n0 = blockIdx.x * 32, m0 = blockIdx.y * 32;
    int x = threadIdx.x, y = threadIdx.y;
    for (int j = y; j < 32; j += 8)
        t[j][x] = src[((size_t)b*NPTS + n0 + j) * KK + m0 + x];
    __syncthreads();
    for (int j = y; j < 32; j += 8)
        dst[((size_t)b*KK + m0 + j) * NPTS + n0 + x] = t[x][j];
}

// ---------------- sinkhorn updates ----------------
__global__ void u_update_kernel() {
    int branch = blockIdx.y;
    const float* C = branch ? g_costf : g_costx;
    const float* v = (branch ? g_v + BB*KK : g_v);
    float* u = (branch ? g_u + BB*NPTS : g_u);
    int r0 = blockIdx.x * 8;
    int b = r0 >> 12;
    __shared__ float vs[64];
    if (threadIdx.x < 64) vs[threadIdx.x] = v[b*KK + threadIdx.x];
    __syncthreads();
    int w = threadIdx.x >> 5, l = threadIdx.x & 31;
    int r = r0 + w;
    const float* Crow = C + (size_t)r * KK;
    float a0 = (vs[l]      - Crow[l])      * INV_EPS;
    float a1 = (vs[l + 32] - Crow[l + 32]) * INV_EPS;
    float mx = fmaxf(a0, a1);
#pragma unroll
    for (int o = 16; o > 0; o >>= 1) mx = fmaxf(mx, __shfl_xor_sync(0xffffffffu, mx, o));
    float s = __expf(a0 - mx) + __expf(a1 - mx);
#pragma unroll
    for (int o = 16; o > 0; o >>= 1) s += __shfl_xor_sync(0xffffffffu, s, o);
    if (l == 0) {
        float epslogp = -SEPS * logf((float)NPTS);
        u[r] = epslogp - SEPS * (mx + logf(s));
    }
}

__global__ void v_update_kernel() {
    int branch = blockIdx.y;
    const float* CT = branch ? g_costfT : g_costxT;
    const float* u = (branch ? g_u + BB*NPTS : g_u);
    float* v = (branch ? g_v + BB*KK : g_v);
    int c = blockIdx.x;          // b*KK + m
    int b = c >> 6;
    const float* row = CT + (size_t)c * NPTS;
    const float* ub = u + b * NPTS;
    int tid = threadIdx.x;
    float vals[16];
    float mx = -1e30f;
#pragma unroll
    for (int i = 0; i < 16; i++) {
        int n = tid + i * 256;
        vals[i] = (ub[n] - row[n]) * INV_EPS;
        mx = fmaxf(mx, vals[i]);
    }
    __shared__ float r[256];
    r[tid] = mx; __syncthreads();
    for (int o = 128; o > 0; o >>= 1) { if (tid < o) r[tid] = fmaxf(r[tid], r[tid+o]); __syncthreads(); }
    mx = r[0]; __syncthreads();
    float s = 0.0f;
#pragma unroll
    for (int i = 0; i < 16; i++) s += __expf(vals[i] - mx);
    r[tid] = s; __syncthreads();
    for (int o = 128; o > 0; o >>= 1) { if (tid < o) r[tid] += r[tid+o]; __syncthreads(); }
    if (tid == 0) {
        float epslogq = -SEPS * logf((float)KK);
        v[c] = epslogq - SEPS * (mx + logf(r[0]));
    }
}

// ---------------- regularizers ----------------
__global__ void reg_xyz_kernel() {
    int b = blockIdx.x, tid = threadIdx.x;
    float local = 0.0f;
    for (int e = tid; e < KK*KK; e += 256) {
        int m1 = e >> 6, m2 = e & 63;
        float s = 0.0f;
#pragma unroll
        for (int d = 0; d < 3; d++)
            s += g_muxyz[(b*3 + d)*KK + m1] * g_muxyz[(b*3 + d)*KK + m2];
        local += fabsf(s - (m1 == m2 ? 1.0f : 0.0f));
    }
    __shared__ float r[256];
    r[tid] = local; __syncthreads();
    for (int o = 128; o > 0; o >>= 1) { if (tid < o) r[tid] += r[tid+o]; __syncthreads(); }
    if (tid == 0) atomicAdd(&g_acc[2], r[0]);
}

__global__ void reg_fea_kernel() {
    int b = blockIdx.x, tid = threadIdx.x;
    float local = 0.0f;
    for (int e = tid; e < KK*KK; e += 256) {
        int m1 = e >> 6, m2 = e & 63;
        const float* p1 = g_mufea + (size_t)b*DD*KK + m1;
        const float* p2 = g_mufea + (size_t)b*DD*KK + m2;
        float s = 0.0f;
#pragma unroll 8
        for (int d = 0; d < DD; d++) s += p1[(size_t)d*KK] * p2[(size_t)d*KK];
        s *= g_invmu[b*KK + m1] * g_invmu[b*KK + m2];
        local += fabsf(s - (m1 == m2 ? 1.0f : 0.0f));
    }
    __shared__ float r[256];
    r[tid] = local; __syncthreads();
    for (int o = 128; o > 0; o >>= 1) { if (tid < o) r[tid] += r[tid+o]; __syncthreads(); }
    if (tid == 0) atomicAdd(&g_acc[3], r[0]);
}

// ---------------- loss: sum over (b,n,m) of gamma * logp ----------------
__global__ void loss_kernel() {
    int branch = blockIdx.y;
    const float* C = branch ? g_costf : g_costx;
    const float* u = (branch ? g_u + BB*NPTS : g_u);
    const float* v = (branch ? g_v + BB*KK : g_v);
    int r0 = blockIdx.x * 8;
    int b = r0 >> 12;
    __shared__ float vs[64];
    if (threadIdx.x < 64) vs[threadIdx.x] = v[b*KK + threadIdx.x];
    __syncthreads();
    int w = threadIdx.x >> 5, l = threadIdx.x & 31;
    int r = r0 + w;
    int n = r & (NPTS - 1);
    const float* Crow = C + (size_t)r * KK;
    float ur = u[r];
    float lsnr = g_lsn[r];
    float acc = 0.0f;
#pragma unroll
    for (int t = 0; t < 2; t++) {
        int m = l + t*32;
        float gma = __expf((ur + vs[m] - Crow[m]) * INV_EPS);
        float lp = g_ls[((size_t)b*KK + m) * NPTS + n] - lsnr;
        acc += gma * lp;
    }
#pragma unroll
    for (int o = 16; o > 0; o >>= 1) acc += __shfl_xor_sync(0xffffffffu, acc, o);
    __shared__ float wsum[8];
    if (l == 0) wsum[w] = acc;
    __syncthreads();
    if (threadIdx.x == 0) {
        float t = 0.0f;
#pragma unroll
        for (int i = 0; i < 8; i++) t += wsum[i];
        atomicAdd(&g_acc[branch], t);
    }
}

__global__ void finalize_kernel(float* __restrict__ out, int out_size) {
    int i = threadIdx.x;
    for (int j = i; j < out_size; j += 32) out[j] = 0.0f;
    __syncwarp();
    if (i == 0) {
        float lx = g_acc[0], lf = g_acc[1], rx = g_acc[2], rf = g_acc[3];
        float loss_xyz = -lx / 8.0f;
        float loss_fea = -lf / 8.0f;
        float reg_fea  = 1e-4f * (rf / (float)(BB*KK*KK));
        float reg_xyz  = 0.001f * 1e-4f * (rx / (float)(BB*KK*KK));
        out[0] = loss_xyz + loss_fea + reg_fea + reg_xyz;
    }
}

// ---------------- launch ----------------
extern "C" void kernel_launch(void* const* d_in, const int* in_sizes, int n_in,
                              void* d_out, int out_size)
{
    const float* feature = (const float*)d_in[0];
    const float* xyz     = (const float*)d_in[1];
    const float* w1      = (const float*)d_in[2];
    const float* b1      = (const float*)d_in[3];
    const float* g1      = (const float*)d_in[4];
    const float* be1     = (const float*)d_in[5];
    const float* w2      = (const float*)d_in[6];
    const float* b2      = (const float*)d_in[7];
    const float* g2      = (const float*)d_in[8];
    const float* be2     = (const float*)d_in[9];
    const float* w3      = (const float*)d_in[10];
    const float* b3      = (const float*)d_in[11];
    float* out = (float*)d_out;

    float* y1 = nullptr; float* y2 = nullptr; float* ls = nullptr;
    cudaGetSymbolAddress((void**)&y1, g_y1);
    cudaGetSymbolAddress((void**)&y2, g_y2);
    cudaGetSymbolAddress((void**)&ls, g_ls);
    float* sc1; float* sh1; float* sc2; float* sh2;
    cudaGetSymbolAddress((void**)&sc1, g_sc1);
    cudaGetSymbolAddress((void**)&sh1, g_sh1);
    cudaGetSymbolAddress((void**)&sc2, g_sc2);
    cudaGetSymbolAddress((void**)&sh2, g_sh2);
    float* cx; float* cxT; float* cf; float* cfT;
    cudaGetSymbolAddress((void**)&cx,  g_costx);
    cudaGetSymbolAddress((void**)&cxT, g_costxT);
    cudaGetSymbolAddress((void**)&cf,  g_costf);
    cudaGetSymbolAddress((void**)&cfT, g_costfT);

    init_kernel<<<(2*BB*NPTS + 255)/256, 256>>>();

    // layer 1
    sgemm_bias_kernel<128,128,8,8,8><<<dim3(NPTS/128, HH/128, BB), 256>>>(w1, feature, b1, y1, HH, DD);
    bn_stats_kernel<<<HH, 256>>>(y1, g1, be1, sc1, sh1);
    bn_relu_kernel<<<(BB*HH*NPTS/4 + 255)/256, 256>>>(y1, sc1, sh1);
    // layer 2
    sgemm_bias_kernel<128,128,8,8,8><<<dim3(NPTS/128, HH/128, BB), 256>>>(w2, y1, b2, y2, HH, HH);
    bn_stats_kernel<<<HH, 256>>>(y2, g2, be2, sc2, sh2);
    bn_relu_kernel<<<(BB*HH*NPTS/4 + 255)/256, 256>>>(y2, sc2, sh2);
    // layer 3 (log_score)
    sgemm_bias_kernel<64,128,8,4,8><<<dim3(NPTS/128, 1, BB), 256>>>(w3, y2, b3, ls, KK, HH);

    softmax_kernel<<<dim3(NPTS/256, BB), 256>>>();
    pi_kernel<<<dim3(KK, BB), 256>>>();
    mu_xyz_kernel<<<dim3(KK, BB), 256>>>(xyz);
    mufea_kernel<<<dim3(DD/64, BB), 256>>>(feature);
    invf_kernel<<<dim3(NPTS/256, BB), 256>>>(feature);
    invmu_kernel<<<BB, 64>>>();
    costf_kernel<<<dim3(NPTS/128, BB), 256>>>(feature);
    costx_kernel<<<dim3(NPTS/8, BB), 256>>>(xyz);
    transpose_kernel<<<dim3(NPTS/32, KK/32, BB), dim3(32, 8)>>>(cx, cxT);
    transpose_kernel<<<dim3(NPTS/32, KK/32, BB), dim3(32, 8)>>>(cf, cfT);

    for (int it = 0; it < 25; it++) {
        u_update_kernel<<<dim3(BB*NPTS/8, 2), 256>>>();
        v_update_kernel<<<dim3(BB*KK, 2), 256>>>();
    }

    reg_xyz_kernel<<<BB, 256>>>();
    reg_fea_kernel<<<BB, 256>>>();
    loss_kernel<<<dim3(BB*NPTS/8, 2), 256>>>();
    finalize_kernel<<<1, 32>>>(out, out_size);
}